// round 6
// baseline (speedup 1.0000x reference)
#include <cuda_runtime.h>
#include <cuda_fp16.h>
#include <cuda_bf16.h>
#include <cstdint>
#include <cstddef>

#define BB 4096
#define NN 8192
#define DD 256

#define SE_SCALE 23.0f     // E int8 scale (max|E| ~5.1 -> 118 < 127)
#define SA_SCALE 127.0f    // A int8 scale (A in [0,1))

// ---- gemm1 tiling (int8) ----
#define MT      64
#define KSPLIT  4
#define KPER    (NN / KSPLIT)     // 2048
#define KC      128               // k per chunk (int8 elems)
#define NCHUNK  (KPER / KC)       // 16
#define A_BYTES (64 * 128)        // 8KB
#define B_BYTES (256 * 128)       // 32KB
#define STG     (A_BYTES + B_BYTES)
#define GEMM_SMEM (3 * STG)       // 122880

// ---- mlp smem ----
#define MLP_IN_PL (128 * 512)
#define MLP_W_PL  (64 * 512)
#define MLP_SMEM  (2 * MLP_IN_PL + 2 * MLP_W_PL)  // 196608

// -------------------- device scratch --------------------
__device__ __align__(256) int   g_labels_s[BB];
__device__ __align__(256) int   g_idx_s[BB];
__device__ int   g_total;
__device__ __align__(256) int   g_rsumI[BB];
__device__ __align__(256) int8_t g_A8[(size_t)BB * NN];    // gathered A rows, int8
__device__ __align__(256) int8_t g_E8[(size_t)DD * NN];    // E transposed, int8 [n][k]
__device__ __align__(256) __nv_bfloat16 g_WHi[3 * DD * DD];
__device__ __align__(256) __nv_bfloat16 g_WLo[3 * DD * DD];
__device__ __align__(256) __nv_bfloat16 g_hHi[BB * DD];
__device__ __align__(256) __nv_bfloat16 g_hLo[BB * DD];
__device__ __align__(256) __nv_bfloat16 g_h2Hi[BB * DD];
__device__ __align__(256) __nv_bfloat16 g_h2Lo[BB * DD];
__device__ __align__(256) float g_part[(size_t)KSPLIT * BB * DD];

// -------------------- helpers --------------------
__device__ __forceinline__ uint32_t smem_u32(const void* p) {
    uint32_t a;
    asm("{ .reg .u64 t; cvta.to.shared.u64 t, %1; cvt.u32.u64 %0, t; }" : "=r"(a) : "l"(p));
    return a;
}
#define CP16(dst, src) \
    asm volatile("cp.async.cg.shared.global [%0], [%1], 16;" \
        :: "r"(dst), "l"(__cvta_generic_to_global(src)) : "memory")
#define CP_COMMIT() asm volatile("cp.async.commit_group;" ::: "memory")

#define LDSM_X4(r0, r1, r2, r3, addr) \
    asm volatile("ldmatrix.sync.aligned.m8n8.x4.shared.b16 {%0,%1,%2,%3}, [%4];" \
        : "=r"(r0), "=r"(r1), "=r"(r2), "=r"(r3) : "r"(addr))

#define MMA_S8(d, a0, a1, a2, a3, b0, b1) \
    asm volatile("mma.sync.aligned.m16n8k32.row.col.s32.s8.s8.s32 " \
        "{%0,%1,%2,%3}, {%4,%5,%6,%7}, {%8,%9}, {%0,%1,%2,%3};" \
        : "+r"((d)[0]), "+r"((d)[1]), "+r"((d)[2]), "+r"((d)[3]) \
        : "r"(a0), "r"(a1), "r"(a2), "r"(a3), "r"(b0), "r"(b1))

#define MMA_BF16(d, a0, a1, a2, a3, b0, b1) \
    asm volatile("mma.sync.aligned.m16n8k16.row.col.f32.bf16.bf16.f32 " \
        "{%0,%1,%2,%3}, {%4,%5,%6,%7}, {%8,%9}, {%0,%1,%2,%3};" \
        : "+f"((d)[0]), "+f"((d)[1]), "+f"((d)[2]), "+f"((d)[3]) \
        : "r"(a0), "r"(a1), "r"(a2), "r"(a3), "r"(b0), "r"(b1))

__device__ __forceinline__ int q8(float v, float s) {
    int q = __float2int_rn(v * s);
    return max(-127, min(127, q));
}

// ==================== 1) stable partition ====================
__global__ void sort_kernel(const int* __restrict__ labels,
                            const int* __restrict__ nidx,
                            float* __restrict__ out_labels) {
    __shared__ int sc[1024];
    int tid = threadIdx.x;
    int g0  = tid * 4;
    int lab[4], nd[4];
    int c = 0;
#pragma unroll
    for (int j = 0; j < 4; j++) {
        lab[j] = labels[g0 + j];
        nd[j]  = nidx[g0 + j];
        c += (lab[j] != 0);
    }
    sc[tid] = c;
    __syncthreads();
    for (int off = 1; off < 1024; off <<= 1) {
        int v = sc[tid];
        int add = (tid >= off) ? sc[tid - off] : 0;
        __syncthreads();
        sc[tid] = v + add;
        __syncthreads();
    }
    int total = sc[1023];
    int p     = sc[tid] - c;
    if (tid == 0) g_total = total;
#pragma unroll
    for (int j = 0; j < 4; j++) {
        int g = g0 + j;
        int dst;
        if (lab[j]) { dst = p; p++; }
        else        { dst = total + (g - p); }
        g_labels_s[dst] = lab[j];
        g_idx_s[dst]    = nd[j];
        if (out_labels) out_labels[dst] = (float)lab[j];
    }
}

// ==================== 2a) E -> int8, transposed [n][k] ====================
__global__ void convE8_kernel(const float* __restrict__ E) {
    __shared__ float tile[64][65];
    const int k0 = blockIdx.x * 64;
    const int n0 = blockIdx.y * 64;
    const int t  = threadIdx.x;
#pragma unroll
    for (int i = 0; i < 16; i++) {
        int idx = t + 256 * i;
        int kl = idx >> 6, nl = idx & 63;
        tile[kl][nl] = E[(size_t)(k0 + kl) * DD + n0 + nl];
    }
    __syncthreads();
    const int nl = t >> 2, w0 = t & 3;
#pragma unroll
    for (int i = 0; i < 4; i++) {
        int w = w0 + i * 4;          // word index 0..15 -> k = w*4
        int k = w * 4;
        int a = q8(tile[k][nl], SE_SCALE);
        int b = q8(tile[k + 1][nl], SE_SCALE);
        int c = q8(tile[k + 2][nl], SE_SCALE);
        int d = q8(tile[k + 3][nl], SE_SCALE);
        uint32_t word = (uint32_t)(a & 0xff) | ((uint32_t)(b & 0xff) << 8) |
                        ((uint32_t)(c & 0xff) << 16) | ((uint32_t)d << 24);
        *reinterpret_cast<uint32_t*>(g_E8 + (size_t)(n0 + nl) * NN + k0 + k) = word;
    }
}

// ==================== 2b) W -> bf16 hi/lo ====================
__global__ void convW_kernel(const float* __restrict__ W) {
    size_t i = (size_t)blockIdx.x * 1024 + threadIdx.x * 4;
    float4 v = *reinterpret_cast<const float4*>(W + i);
    float f[4] = {v.x, v.y, v.z, v.w};
#pragma unroll
    for (int j = 0; j < 4; j++) {
        __nv_bfloat16 hi = __float2bfloat16_rn(f[j]);
        __nv_bfloat16 lo = __float2bfloat16_rn(f[j] - __bfloat162float(hi));
        g_WHi[i + j] = hi;
        g_WLo[i + j] = lo;
    }
}

// ==================== 2c) gather A rows -> int8 + exact int rowsum ====================
__global__ void __launch_bounds__(256) convA8_kernel(const float* __restrict__ A) {
    const int row = blockIdx.x;
    if (row >= g_total) return;
    const int t    = threadIdx.x;
    const int node = g_idx_s[row];
    const float* src = A + (size_t)node * NN;
    int s = 0;
#pragma unroll
    for (int i = 0; i < 8; i++) {
        size_t idx = (size_t)t * 4 + (size_t)i * 1024;
        float4 v = *reinterpret_cast<const float4*>(src + idx);
        int a = q8(v.x, SA_SCALE);
        int b = q8(v.y, SA_SCALE);
        int c = q8(v.z, SA_SCALE);
        int d = q8(v.w, SA_SCALE);
        s += a + b + c + d;
        uint32_t word = (uint32_t)(a & 0xff) | ((uint32_t)(b & 0xff) << 8) |
                        ((uint32_t)(c & 0xff) << 16) | ((uint32_t)d << 24);
        *reinterpret_cast<uint32_t*>(g_A8 + (size_t)row * NN + idx) = word;
    }
#pragma unroll
    for (int off = 16; off > 0; off >>= 1)
        s += __shfl_down_sync(0xffffffffu, s, off);
    __shared__ int ws[8];
    if ((t & 31) == 0) ws[t >> 5] = s;
    __syncthreads();
    if (t == 0) {
        int tot = 0;
#pragma unroll
        for (int w = 0; w < 8; w++) tot += ws[w];
        g_rsumI[row] = tot;
    }
}

// ==================== 3) int8 tensor GEMM: part[kb] = A8 @ E8^T ====================
// grid (KSPLIT, BB/MT): kb fast axis so all active M-tiles pack into wave 1.
__global__ void __launch_bounds__(256, 1) gemm1_kernel() {
    const int kb = blockIdx.x;
    const int m0 = blockIdx.y * MT;
    if (m0 >= g_total) return;

    extern __shared__ __align__(1024) char smem[];
    const uint32_t sb = smem_u32(smem);
    const int t = threadIdx.x, lane = t & 31, wid = t >> 5;
    const int wm = wid & 3, wn = wid >> 2;
    const size_t kBase = (size_t)kb * KPER;

    int acc[16][4];
#pragma unroll
    for (int f = 0; f < 16; f++)
#pragma unroll
        for (int r = 0; r < 4; r++) acc[f][r] = 0;

    auto load_stage = [&](int c) {
        const uint32_t base = sb + (uint32_t)((c % 3) * STG);
        const size_t kOff = kBase + (size_t)c * KC;
#pragma unroll
        for (int i = 0; i < 2; i++) {             // A: 512 x 16B granules
            int g = t + 256 * i;
            int m = g >> 3, s8 = g & 7;
            uint32_t dst = base + m * 128 + (uint32_t)((s8 * 16) ^ ((m & 7) << 4));
            CP16(dst, g_A8 + (size_t)(m0 + m) * NN + kOff + s8 * 16);
        }
#pragma unroll
        for (int i = 0; i < 8; i++) {             // B: 2048 x 16B granules
            int g = t + 256 * i;
            int n = g >> 3, s8 = g & 7;
            uint32_t dst = base + A_BYTES + n * 128 + (uint32_t)((s8 * 16) ^ ((n & 7) << 4));
            CP16(dst, g_E8 + (size_t)n * NN + kOff + s8 * 16);
        }
    };

    auto compute_stage = [&](int c) {
        const uint32_t Ab = sb + (uint32_t)((c % 3) * STG);
        const uint32_t Bb = Ab + A_BYTES;
        const int q = lane >> 3, l7 = lane & 7;
        // B ldmatrix lane mapping: matrix (lane>>3): 0:(n0..7,k0) 1:(n0..7,k16) 2:(n8..15,k0) 3:(n8..15,k16)
        const int bnr = wn * 128 + ((lane >> 4) << 3) + l7;
        const int bkh = ((lane >> 3) & 1) * 16;
#pragma unroll
        for (int ks = 0; ks < 4; ks++) {
            const int am  = wm * 16 + (q & 1) * 8 + l7;
            const int akB = ks * 32 + (q >> 1) * 16;
            uint32_t a0, a1, a2, a3;
            LDSM_X4(a0, a1, a2, a3, Ab + am * 128 + (uint32_t)(akB ^ ((am & 7) << 4)));
            const int kbB = ks * 32 + bkh;
#pragma unroll
            for (int jb = 0; jb < 8; jb++) {
                const int nrow = bnr + jb * 16;
                uint32_t b0, b1, b2, b3;
                LDSM_X4(b0, b1, b2, b3,
                        Bb + nrow * 128 + (uint32_t)(kbB ^ ((nrow & 7) << 4)));
                MMA_S8(acc[jb * 2],     a0, a1, a2, a3, b0, b1);
                MMA_S8(acc[jb * 2 + 1], a0, a1, a2, a3, b2, b3);
            }
        }
    };

    load_stage(0); CP_COMMIT();
    load_stage(1); CP_COMMIT();
    load_stage(2); CP_COMMIT();
    for (int c = 0; c < NCHUNK; c++) {
        asm volatile("cp.async.wait_group 2;" ::: "memory");
        __syncthreads();
        compute_stage(c);
        __syncthreads();
        if (c + 3 < NCHUNK) load_stage(c + 3);
        CP_COMMIT();
    }

    float* pbase = g_part + ((size_t)kb * BB + m0) * DD;
    const int row = wm * 16 + (lane >> 2);
    const int cb  = wn * 128 + (lane & 3) * 2;
#pragma unroll
    for (int f = 0; f < 16; f++) {
        const int n = cb + f * 8;
        *reinterpret_cast<float2*>(pbase + (size_t)row * DD + n) =
            make_float2((float)acc[f][0], (float)acc[f][1]);
        *reinterpret_cast<float2*>(pbase + (size_t)(row + 8) * DD + n) =
            make_float2((float)acc[f][2], (float)acc[f][3]);
    }
}

// ==================== 4) finalize: reduce, dequant-normalize, gather, bf16-split ====================
__global__ void finalize_kernel(const float* __restrict__ E) {
    const int b = blockIdx.x;
    const int t = threadIdx.x;   // 64 threads x 4 elems
    const int lab  = g_labels_s[b];
    const int node = g_idx_s[b];
    float v[4];
    if (lab) {
        // agg = dot_int / (sE * irsum)  (sA cancels exactly)
        float inv = 1.0f / (SE_SCALE * (float)g_rsumI[b]);
        v[0] = v[1] = v[2] = v[3] = 0.f;
#pragma unroll
        for (int kb = 0; kb < KSPLIT; kb++) {
            float4 p = *reinterpret_cast<const float4*>(
                g_part + ((size_t)kb * BB + b) * DD + t * 4);
            v[0] += p.x; v[1] += p.y; v[2] += p.z; v[3] += p.w;
        }
#pragma unroll
        for (int j = 0; j < 4; j++) v[j] *= inv;
    } else {
        float4 p = *reinterpret_cast<const float4*>(E + (size_t)node * DD + t * 4);
        v[0] = p.x; v[1] = p.y; v[2] = p.z; v[3] = p.w;
    }
    size_t o = (size_t)b * DD + t * 4;
#pragma unroll
    for (int j = 0; j < 4; j++) {
        __nv_bfloat16 hi = __float2bfloat16_rn(v[j]);
        __nv_bfloat16 lo = __float2bfloat16_rn(v[j] - __bfloat162float(hi));
        g_hHi[o + j] = hi;
        g_hLo[o + j] = lo;
    }
}

// ==================== 5) MLP layer: bf16x3 emulated-fp32 GEMM + bias + relu ====================
__global__ void __launch_bounds__(256, 1) mlp_kernel(
    const __nv_bfloat16* __restrict__ inHi, const __nv_bfloat16* __restrict__ inLo,
    const __nv_bfloat16* __restrict__ WHi,  const __nv_bfloat16* __restrict__ WLo,
    const float* __restrict__ bias,
    __nv_bfloat16* __restrict__ outHi, __nv_bfloat16* __restrict__ outLo,
    float* __restrict__ outF) {
    const int i0 = blockIdx.x * 128;
    const int o0 = blockIdx.y * 64;
    extern __shared__ __align__(1024) char smem[];
    const uint32_t sb = smem_u32(smem);
    const int t = threadIdx.x, lane = t & 31, wid = t >> 5;
    const int wm = wid & 3, wn = wid >> 2;
    const uint32_t sINhi = sb;
    const uint32_t sINlo = sb + MLP_IN_PL;
    const uint32_t sWhi  = sb + 2 * MLP_IN_PL;
    const uint32_t sWlo  = sWhi + MLP_W_PL;

    auto load_half = [&](int h) {
#pragma unroll
        for (int i = 0; i < 8; i++) {
            int g = t + 256 * i;
            int m = g >> 4, s = (g & 15) + h * 16;
            uint32_t off = m * 512 + (uint32_t)((s * 16) ^ ((m & 7) << 4));
            CP16(sINhi + off, inHi + (size_t)(i0 + m) * DD + s * 8);
            CP16(sINlo + off, inLo + (size_t)(i0 + m) * DD + s * 8);
        }
#pragma unroll
        for (int i = 0; i < 4; i++) {
            int g = t + 256 * i;
            int n = g >> 4, s = (g & 15) + h * 16;
            uint32_t off = n * 512 + (uint32_t)((s * 16) ^ ((n & 7) << 4));
            CP16(sWhi + off, WHi + (size_t)(o0 + n) * DD + s * 8);
            CP16(sWlo + off, WLo + (size_t)(o0 + n) * DD + s * 8);
        }
    };

    float acc[2][4][4];
#pragma unroll
    for (int mm = 0; mm < 2; mm++)
#pragma unroll
        for (int f = 0; f < 4; f++)
#pragma unroll
            for (int r = 0; r < 4; r++) acc[mm][f][r] = 0.f;

    auto comp_half = [&](int h) {
        const int q = lane >> 3, l7 = lane & 7;
#pragma unroll
        for (int ksl = 0; ksl < 8; ksl++) {
            const int ks = h * 8 + ksl;
            uint32_t ah[2][4], al[2][4];
#pragma unroll
            for (int mm = 0; mm < 2; mm++) {
                const int m  = wm * 32 + mm * 16 + (q & 1) * 8 + l7;
                const int kB = ks * 32 + (q >> 1) * 16;
                const uint32_t off = m * 512 + (uint32_t)(kB ^ ((m & 7) << 4));
                LDSM_X4(ah[mm][0], ah[mm][1], ah[mm][2], ah[mm][3], sINhi + off);
                LDSM_X4(al[mm][0], al[mm][1], al[mm][2], al[mm][3], sINlo + off);
            }
            uint32_t bh[2][4], bl[2][4];
#pragma unroll
            for (int nn = 0; nn < 2; nn++) {
                const int n  = wn * 32 + nn * 16 + (q >> 1) * 8 + l7;
                const int kB = ks * 32 + (q & 1) * 16;
                const uint32_t off = n * 512 + (uint32_t)(kB ^ ((n & 7) << 4));
                LDSM_X4(bh[nn][0], bh[nn][1], bh[nn][2], bh[nn][3], sWhi + off);
                LDSM_X4(bl[nn][0], bl[nn][1], bl[nn][2], bl[nn][3], sWlo + off);
            }
#pragma unroll
            for (int mm = 0; mm < 2; mm++)
#pragma unroll
                for (int nn = 0; nn < 2; nn++) {
                    float* d0 = acc[mm][nn * 2];
                    float* d1 = acc[mm][nn * 2 + 1];
                    MMA_BF16(d0, ah[mm][0], ah[mm][1], ah[mm][2], ah[mm][3], bh[nn][0], bh[nn][1]);
                    MMA_BF16(d0, al[mm][0], al[mm][1], al[mm][2], al[mm][3], bh[nn][0], bh[nn][1]);
                    MMA_BF16(d0, ah[mm][0], ah[mm][1], ah[mm][2], ah[mm][3], bl[nn][0], bl[nn][1]);
                    MMA_BF16(d1, ah[mm][0], ah[mm][1], ah[mm][2], ah[mm][3], bh[nn][2], bh[nn][3]);
                    MMA_BF16(d1, al[mm][0], al[mm][1], al[mm][2], al[mm][3], bh[nn][2], bh[nn][3]);
                    MMA_BF16(d1, ah[mm][0], ah[mm][1], ah[mm][2], ah[mm][3], bl[nn][2], bl[nn][3]);
                }
        }
    };

    load_half(0); CP_COMMIT();
    load_half(1); CP_COMMIT();
    asm volatile("cp.async.wait_group 1;" ::: "memory");
    __syncthreads();
    comp_half(0);
    asm volatile("cp.async.wait_group 0;" ::: "memory");
    __syncthreads();
    comp_half(1);

#pragma unroll
    for (int mm = 0; mm < 2; mm++) {
        const int row0 = i0 + wm * 32 + mm * 16 + (lane >> 2);
#pragma unroll
        for (int f = 0; f < 4; f++) {
            const int col = o0 + wn * 32 + f * 8 + (lane & 3) * 2;
            const float b0 = bias[col], b1 = bias[col + 1];
            float y00 = fmaxf(acc[mm][f][0] + b0, 0.f);
            float y01 = fmaxf(acc[mm][f][1] + b1, 0.f);
            float y10 = fmaxf(acc[mm][f][2] + b0, 0.f);
            float y11 = fmaxf(acc[mm][f][3] + b1, 0.f);
            if (outF) {
                *reinterpret_cast<float2*>(outF + (size_t)row0 * DD + col) = make_float2(y00, y01);
                *reinterpret_cast<float2*>(outF + (size_t)(row0 + 8) * DD + col) = make_float2(y10, y11);
            } else {
                float y[4] = {y00, y01, y10, y11};
                __nv_bfloat16 hi[4], lo[4];
#pragma unroll
                for (int j = 0; j < 4; j++) {
                    hi[j] = __float2bfloat16_rn(y[j]);
                    lo[j] = __float2bfloat16_rn(y[j] - __bfloat162float(hi[j]));
                }
                *reinterpret_cast<__nv_bfloat162*>(outHi + (size_t)row0 * DD + col) = __halves2bfloat162(hi[0], hi[1]);
                *reinterpret_cast<__nv_bfloat162*>(outHi + (size_t)(row0 + 8) * DD + col) = __halves2bfloat162(hi[2], hi[3]);
                *reinterpret_cast<__nv_bfloat162*>(outLo + (size_t)row0 * DD + col) = __halves2bfloat162(lo[0], lo[1]);
                *reinterpret_cast<__nv_bfloat162*>(outLo + (size_t)(row0 + 8) * DD + col) = __halves2bfloat162(lo[2], lo[3]);
            }
        }
    }
}

// ==================== launch ====================
extern "C" void kernel_launch(void* const* d_in, const int* in_sizes, int n_in,
                              void* d_out, int out_size) {
    const int*   labels = (const int*)d_in[0];
    const int*   nidx   = (const int*)d_in[1];
    const float* A      = (const float*)d_in[2];
    const float* E      = (const float*)d_in[3];
    const float* W      = (const float*)d_in[4];
    const float* bias   = (const float*)d_in[5];

    float* out        = (float*)d_out;
    float* out_labels = nullptr;
    float* out_h      = out;
    if (out_size >= BB * DD + BB) {
        out_labels = out;
        out_h      = out + BB;
    }

    __nv_bfloat16 *hHi, *hLo, *h2Hi, *h2Lo, *WHi, *WLo;
    cudaGetSymbolAddress((void**)&hHi,  g_hHi);
    cudaGetSymbolAddress((void**)&hLo,  g_hLo);
    cudaGetSymbolAddress((void**)&h2Hi, g_h2Hi);
    cudaGetSymbolAddress((void**)&h2Lo, g_h2Lo);
    cudaGetSymbolAddress((void**)&WHi,  g_WHi);
    cudaGetSymbolAddress((void**)&WLo,  g_WLo);

    cudaFuncSetAttribute(gemm1_kernel,
                         cudaFuncAttributeMaxDynamicSharedMemorySize, GEMM_SMEM);
    cudaFuncSetAttribute(mlp_kernel,
                         cudaFuncAttributeMaxDynamicSharedMemorySize, MLP_SMEM);

    sort_kernel<<<1, 1024>>>(labels, nidx, out_labels);
    convE8_kernel<<<dim3(NN / 64, DD / 64), 256>>>(E);
    convW_kernel<<<(3 * DD * DD) / 1024, 256>>>(W);
    convA8_kernel<<<BB, 256>>>(A);
    gemm1_kernel<<<dim3(KSPLIT, BB / MT), 256, GEMM_SMEM>>>();
    finalize_kernel<<<BB, 64>>>(E);
    mlp_kernel<<<dim3(BB / 128, DD / 64), 256, MLP_SMEM>>>(
        hHi, hLo, WHi, WLo, bias, h2Hi, h2Lo, nullptr);
    mlp_kernel<<<dim3(BB / 128, DD / 64), 256, MLP_SMEM>>>(
        h2Hi, h2Lo, WHi + DD * DD, WLo + DD * DD, bias + DD, hHi, hLo, nullptr);
    mlp_kernel<<<dim3(BB / 128, DD / 64), 256, MLP_SMEM>>>(
        hHi, hLo, WHi + 2 * DD * DD, WLo + 2 * DD * DD, bias + 2 * DD,
        nullptr, nullptr, out_h);
}

// round 7
// speedup vs baseline: 1.4927x; 1.4927x over previous
#include <cuda_runtime.h>
#include <cuda_fp16.h>
#include <cuda_bf16.h>
#include <cstdint>
#include <cstddef>

#define BB 4096
#define NN 8192
#define DD 256

// ---- gemm1 tiling (fp16) ----
#define MT      64
#define KSPLIT  4
#define KPER    (NN / KSPLIT)     // 2048
#define KC      64
#define NCHUNK  (KPER / KC)       // 32
#define A_BYTES (64 * 128)        // 64 rows x 64 fp16
#define B_BYTES (64 * 512)        // 64 k-rows x 256 fp16
#define STG     (A_BYTES + B_BYTES)
#define GEMM_SMEM (3 * STG)       // 122880

// ---- mlp smem ----
#define MLP_IN_PL (128 * 512)
#define MLP_W_PL  (64 * 512)
#define MLP_SMEM  (2 * MLP_IN_PL + 2 * MLP_W_PL)  // 196608

// ---- prep kernel block dispatch ----
#define PREP_SORT   0
#define PREP_CONVA  1                       // 4096 blocks, b = bid-1
#define PREP_CONVE  (PREP_CONVA + BB)       // 2048 blocks
#define PREP_CONVW  (PREP_CONVE + (NN * DD) / 1024)
#define PREP_GRID   (PREP_CONVW + (3 * DD * DD) / 1024)

// -------------------- device scratch --------------------
__device__ __align__(256) int   g_labels_s[BB];
__device__ __align__(256) int   g_idx_s[BB];
__device__ __align__(256) int   g_perm[BB];     // sorted pos -> original batch idx
__device__ int   g_total;
__device__ __align__(256) float g_rsumF[BB];    // indexed by ORIGINAL batch idx
__device__ __align__(256) __half g_Ah[(size_t)BB * NN];   // indexed by ORIGINAL batch idx
__device__ __align__(256) __half g_Eh[(size_t)NN * DD];
__device__ __align__(256) __nv_bfloat16 g_WHi[3 * DD * DD];
__device__ __align__(256) __nv_bfloat16 g_WLo[3 * DD * DD];
__device__ __align__(256) __nv_bfloat16 g_hHi[BB * DD];
__device__ __align__(256) __nv_bfloat16 g_hLo[BB * DD];
__device__ __align__(256) __nv_bfloat16 g_h2Hi[BB * DD];
__device__ __align__(256) __nv_bfloat16 g_h2Lo[BB * DD];
__device__ __align__(256) float g_part[(size_t)KSPLIT * BB * DD];

// -------------------- helpers --------------------
__device__ __forceinline__ uint32_t smem_u32(const void* p) {
    uint32_t a;
    asm("{ .reg .u64 t; cvta.to.shared.u64 t, %1; cvt.u32.u64 %0, t; }" : "=r"(a) : "l"(p));
    return a;
}
#define CP16(dst, src) \
    asm volatile("cp.async.cg.shared.global [%0], [%1], 16;" \
        :: "r"(dst), "l"(__cvta_generic_to_global(src)) : "memory")
#define CP_COMMIT() asm volatile("cp.async.commit_group;" ::: "memory")

#define LDSM_X4(r0, r1, r2, r3, addr) \
    asm volatile("ldmatrix.sync.aligned.m8n8.x4.shared.b16 {%0,%1,%2,%3}, [%4];" \
        : "=r"(r0), "=r"(r1), "=r"(r2), "=r"(r3) : "r"(addr))
#define LDSM_X4_T(r0, r1, r2, r3, addr) \
    asm volatile("ldmatrix.sync.aligned.m8n8.x4.trans.shared.b16 {%0,%1,%2,%3}, [%4];" \
        : "=r"(r0), "=r"(r1), "=r"(r2), "=r"(r3) : "r"(addr))

#define MMA_F16(d, a0, a1, a2, a3, b0, b1) \
    asm volatile("mma.sync.aligned.m16n8k16.row.col.f32.f16.f16.f32 " \
        "{%0,%1,%2,%3}, {%4,%5,%6,%7}, {%8,%9}, {%0,%1,%2,%3};" \
        : "+f"((d)[0]), "+f"((d)[1]), "+f"((d)[2]), "+f"((d)[3]) \
        : "r"(a0), "r"(a1), "r"(a2), "r"(a3), "r"(b0), "r"(b1))

#define MMA_BF16(d, a0, a1, a2, a3, b0, b1) \
    asm volatile("mma.sync.aligned.m16n8k16.row.col.f32.bf16.bf16.f32 " \
        "{%0,%1,%2,%3}, {%4,%5,%6,%7}, {%8,%9}, {%0,%1,%2,%3};" \
        : "+f"((d)[0]), "+f"((d)[1]), "+f"((d)[2]), "+f"((d)[3]) \
        : "r"(a0), "r"(a1), "r"(a2), "r"(a3), "r"(b0), "r"(b1))

// ==================== 1) fused prep: sort + convA + convE + convW ====================
__global__ void __launch_bounds__(256) prep_kernel(
    const int* __restrict__ labels, const int* __restrict__ nidx,
    const float* __restrict__ A,    const float* __restrict__ E,
    const float* __restrict__ W,    float* __restrict__ out_labels) {
    const int bid = blockIdx.x;
    const int t   = threadIdx.x;

    if (bid == PREP_SORT) {
        // ---- stable partition: positives first (256 threads x 16 elems) ----
        __shared__ int sc[256];
        int g0 = t * 16;
        int lab[16], nd[16];
        int c = 0;
#pragma unroll
        for (int j = 0; j < 16; j++) {
            lab[j] = labels[g0 + j];
            nd[j]  = nidx[g0 + j];
            c += (lab[j] != 0);
        }
        sc[t] = c;
        __syncthreads();
        for (int off = 1; off < 256; off <<= 1) {
            int v = sc[t];
            int add = (t >= off) ? sc[t - off] : 0;
            __syncthreads();
            sc[t] = v + add;
            __syncthreads();
        }
        int total = sc[255];
        int p     = sc[t] - c;
        if (t == 0) g_total = total;
#pragma unroll
        for (int j = 0; j < 16; j++) {
            int g = g0 + j;
            int dst;
            if (lab[j]) { dst = p; p++; }
            else        { dst = total + (g - p); }
            g_labels_s[dst] = lab[j];
            g_idx_s[dst]    = nd[j];
            g_perm[dst]     = g;
            if (out_labels) out_labels[dst] = (float)lab[j];
        }
    } else if (bid < PREP_CONVE) {
        // ---- convA: gather positive A rows -> fp16 (unsorted index) ----
        const int b = bid - PREP_CONVA;
        if (labels[b] == 0) return;
        const int node = nidx[b];
        const float* src = A + (size_t)node * NN;
        __half* dst = g_Ah + (size_t)b * NN;
        float s = 0.f;
#pragma unroll
        for (int i = 0; i < 8; i++) {
            size_t idx = (size_t)t * 4 + (size_t)i * 1024;
            float4 v = *reinterpret_cast<const float4*>(src + idx);
            __half2 h0 = __float22half2_rn(make_float2(v.x, v.y));
            __half2 h1 = __float22half2_rn(make_float2(v.z, v.w));
            __half2* d = reinterpret_cast<__half2*>(dst + idx);
            d[0] = h0; d[1] = h1;
            float2 f0 = __half22float2(h0), f1 = __half22float2(h1);
            s += (f0.x + f0.y) + (f1.x + f1.y);
        }
#pragma unroll
        for (int off = 16; off > 0; off >>= 1)
            s += __shfl_down_sync(0xffffffffu, s, off);
        __shared__ float ws[8];
        if ((t & 31) == 0) ws[t >> 5] = s;
        __syncthreads();
        if (t == 0) {
            float tot = 0.f;
#pragma unroll
            for (int w = 0; w < 8; w++) tot += ws[w];
            g_rsumF[b] = tot;
        }
    } else if (bid < PREP_CONVW) {
        // ---- convE: E -> fp16 ----
        size_t i = (size_t)(bid - PREP_CONVE) * 1024 + t * 4;
        float4 v = *reinterpret_cast<const float4*>(E + i);
        __half2* dst = reinterpret_cast<__half2*>(g_Eh + i);
        dst[0] = __float22half2_rn(make_float2(v.x, v.y));
        dst[1] = __float22half2_rn(make_float2(v.z, v.w));
    } else {
        // ---- convW: W -> bf16 hi/lo ----
        size_t i = (size_t)(bid - PREP_CONVW) * 1024 + t * 4;
        float4 v = *reinterpret_cast<const float4*>(W + i);
        float f[4] = {v.x, v.y, v.z, v.w};
#pragma unroll
        for (int j = 0; j < 4; j++) {
            __nv_bfloat16 hi = __float2bfloat16_rn(f[j]);
            __nv_bfloat16 lo = __float2bfloat16_rn(f[j] - __bfloat162float(hi));
            g_WHi[i + j] = hi;
            g_WLo[i + j] = lo;
        }
    }
}

// ==================== 2) fp16 tensor GEMM: part[kb] = Ah(gathered) @ Eh ====================
// grid (KSPLIT, BB/MT): kb fast axis -> all active M-tiles pack into wave 1.
__global__ void __launch_bounds__(256, 1) gemm1_kernel() {
    const int kb = blockIdx.x;
    const int m0 = blockIdx.y * MT;
    if (m0 >= g_total) return;

    extern __shared__ __align__(1024) char smem[];
    const uint32_t sb = smem_u32(smem);
    const int t = threadIdx.x, lane = t & 31, wid = t >> 5;
    const int wm = wid & 3, wn = wid >> 2;
    const size_t kBase = (size_t)kb * KPER;

    // per-thread gathered A row pointers (rows t>>3 and 32+(t>>3) of this tile)
    const int mA = t >> 3;
    const __half* rowA0 = g_Ah + (size_t)g_perm[m0 + mA] * NN;
    const __half* rowA1 = g_Ah + (size_t)g_perm[m0 + mA + 32] * NN;

    float acc[16][4];
#pragma unroll
    for (int f = 0; f < 16; f++)
#pragma unroll
        for (int r = 0; r < 4; r++) acc[f][r] = 0.f;

    auto load_stage = [&](int c) {
        const uint32_t base = sb + (uint32_t)((c % 3) * STG);
        const size_t kOff = kBase + (size_t)c * KC;
        const int s8 = t & 7;
        {   // A: rows mA and mA+32
            uint32_t d0 = base + mA * 128 + (uint32_t)((s8 * 16) ^ ((mA & 7) << 4));
            CP16(d0, rowA0 + kOff + s8 * 8);
            const int m1 = mA + 32;
            uint32_t d1 = base + m1 * 128 + (uint32_t)((s8 * 16) ^ ((m1 & 7) << 4));
            CP16(d1, rowA1 + kOff + s8 * 8);
        }
#pragma unroll
        for (int i = 0; i < 8; i++) {             // B: 2048 granules
            int g = t + 256 * i;
            int k = g >> 5, ns = g & 31;
            uint32_t dst = base + A_BYTES + k * 512 + (uint32_t)((ns * 16) ^ ((k & 7) << 4));
            CP16(dst, g_Eh + (kOff + k) * DD + ns * 8);
        }
    };

    auto compute_stage = [&](int c) {
        const uint32_t Ab = sb + (uint32_t)((c % 3) * STG);
        const uint32_t Bb = Ab + A_BYTES;
        const int q = lane >> 3, l7 = lane & 7;
#pragma unroll
        for (int ks = 0; ks < 4; ks++) {
            const int am  = wm * 16 + (q & 1) * 8 + l7;
            const int akB = ks * 32 + (q >> 1) * 16;
            uint32_t a0, a1, a2, a3;
            LDSM_X4(a0, a1, a2, a3, Ab + am * 128 + (uint32_t)(akB ^ ((am & 7) << 4)));
            const int bk = ks * 16 + (q & 1) * 8 + l7;
            const uint32_t brow = Bb + bk * 512;
            const uint32_t bxor = (uint32_t)((bk & 7) << 4);
#pragma unroll
            for (int jb = 0; jb < 8; jb++) {
                const uint32_t nB = (uint32_t)((wn * 128 + jb * 16 + (q >> 1) * 8) * 2);
                uint32_t b0, b1, b2, b3;
                LDSM_X4_T(b0, b1, b2, b3, brow + (nB ^ bxor));
                MMA_F16(acc[jb * 2],     a0, a1, a2, a3, b0, b1);
                MMA_F16(acc[jb * 2 + 1], a0, a1, a2, a3, b2, b3);
            }
        }
    };

    load_stage(0); CP_COMMIT();
    load_stage(1); CP_COMMIT();
    load_stage(2); CP_COMMIT();
    for (int c = 0; c < NCHUNK; c++) {
        asm volatile("cp.async.wait_group 2;" ::: "memory");
        __syncthreads();
        compute_stage(c);
        __syncthreads();
        if (c + 3 < NCHUNK) load_stage(c + 3);
        CP_COMMIT();
    }

    float* pbase = g_part + ((size_t)kb * BB + m0) * DD;
    const int row = wm * 16 + (lane >> 2);
    const int cb  = wn * 128 + (lane & 3) * 2;
#pragma unroll
    for (int f = 0; f < 16; f++) {
        const int n = cb + f * 8;
        *reinterpret_cast<float2*>(pbase + (size_t)row * DD + n) =
            make_float2(acc[f][0], acc[f][1]);
        *reinterpret_cast<float2*>(pbase + (size_t)(row + 8) * DD + n) =
            make_float2(acc[f][2], acc[f][3]);
    }
}

// ==================== 3) finalize: reduce, normalize, gather, bf16-split ====================
__global__ void finalize_kernel(const float* __restrict__ E) {
    const int b = blockIdx.x;
    const int t = threadIdx.x;   // 64 threads x 4 elems
    const int lab  = g_labels_s[b];
    const int node = g_idx_s[b];
    float v[4];
    if (lab) {
        float inv = 1.0f / g_rsumF[g_perm[b]];
        v[0] = v[1] = v[2] = v[3] = 0.f;
#pragma unroll
        for (int kb = 0; kb < KSPLIT; kb++) {
            float4 p = *reinterpret_cast<const float4*>(
                g_part + ((size_t)kb * BB + b) * DD + t * 4);
            v[0] += p.x; v[1] += p.y; v[2] += p.z; v[3] += p.w;
        }
#pragma unroll
        for (int j = 0; j < 4; j++) v[j] *= inv;
    } else {
        float4 p = *reinterpret_cast<const float4*>(E + (size_t)node * DD + t * 4);
        v[0] = p.x; v[1] = p.y; v[2] = p.z; v[3] = p.w;
    }
    size_t o = (size_t)b * DD + t * 4;
#pragma unroll
    for (int j = 0; j < 4; j++) {
        __nv_bfloat16 hi = __float2bfloat16_rn(v[j]);
        __nv_bfloat16 lo = __float2bfloat16_rn(v[j] - __bfloat162float(hi));
        g_hHi[o + j] = hi;
        g_hLo[o + j] = lo;
    }
}

// ==================== 4) MLP layer: bf16x3 emulated-fp32 GEMM + bias + relu ====================
__global__ void __launch_bounds__(256, 1) mlp_kernel(
    const __nv_bfloat16* __restrict__ inHi, const __nv_bfloat16* __restrict__ inLo,
    const __nv_bfloat16* __restrict__ WHi,  const __nv_bfloat16* __restrict__ WLo,
    const float* __restrict__ bias,
    __nv_bfloat16* __restrict__ outHi, __nv_bfloat16* __restrict__ outLo,
    float* __restrict__ outF) {
    const int i0 = blockIdx.x * 128;
    const int o0 = blockIdx.y * 64;
    extern __shared__ __align__(1024) char smem[];
    const uint32_t sb = smem_u32(smem);
    const int t = threadIdx.x, lane = t & 31, wid = t >> 5;
    const int wm = wid & 3, wn = wid >> 2;
    const uint32_t sINhi = sb;
    const uint32_t sINlo = sb + MLP_IN_PL;
    const uint32_t sWhi  = sb + 2 * MLP_IN_PL;
    const uint32_t sWlo  = sWhi + MLP_W_PL;

    auto load_half = [&](int h) {
#pragma unroll
        for (int i = 0; i < 8; i++) {
            int g = t + 256 * i;
            int m = g >> 4, s = (g & 15) + h * 16;
            uint32_t off = m * 512 + (uint32_t)((s * 16) ^ ((m & 7) << 4));
            CP16(sINhi + off, inHi + (size_t)(i0 + m) * DD + s * 8);
            CP16(sINlo + off, inLo + (size_t)(i0 + m) * DD + s * 8);
        }
#pragma unroll
        for (int i = 0; i < 4; i++) {
            int g = t + 256 * i;
            int n = g >> 4, s = (g & 15) + h * 16;
            uint32_t off = n * 512 + (uint32_t)((s * 16) ^ ((n & 7) << 4));
            CP16(sWhi + off, WHi + (size_t)(o0 + n) * DD + s * 8);
            CP16(sWlo + off, WLo + (size_t)(o0 + n) * DD + s * 8);
        }
    };

    float acc[2][4][4];
#pragma unroll
    for (int mm = 0; mm < 2; mm++)
#pragma unroll
        for (int f = 0; f < 4; f++)
#pragma unroll
            for (int r = 0; r < 4; r++) acc[mm][f][r] = 0.f;

    auto comp_half = [&](int h) {
        const int q = lane >> 3, l7 = lane & 7;
#pragma unroll
        for (int ksl = 0; ksl < 8; ksl++) {
            const int ks = h * 8 + ksl;
            uint32_t ah[2][4], al[2][4];
#pragma unroll
            for (int mm = 0; mm < 2; mm++) {
                const int m  = wm * 32 + mm * 16 + (q & 1) * 8 + l7;
                const int kB = ks * 32 + (q >> 1) * 16;
                const uint32_t off = m * 512 + (uint32_t)(kB ^ ((m & 7) << 4));
                LDSM_X4(ah[mm][0], ah[mm][1], ah[mm][2], ah[mm][3], sINhi + off);
                LDSM_X4(al[mm][0], al[mm][1], al[mm][2], al[mm][3], sINlo + off);
            }
            uint32_t bh[2][4], bl[2][4];
#pragma unroll
            for (int nn = 0; nn < 2; nn++) {
                const int n  = wn * 32 + nn * 16 + (q >> 1) * 8 + l7;
                const int kB = ks * 32 + (q & 1) * 16;
                const uint32_t off = n * 512 + (uint32_t)(kB ^ ((n & 7) << 4));
                LDSM_X4(bh[nn][0], bh[nn][1], bh[nn][2], bh[nn][3], sWhi + off);
                LDSM_X4(bl[nn][0], bl[nn][1], bl[nn][2], bl[nn][3], sWlo + off);
            }
#pragma unroll
            for (int mm = 0; mm < 2; mm++)
#pragma unroll
                for (int nn = 0; nn < 2; nn++) {
                    float* d0 = acc[mm][nn * 2];
                    float* d1 = acc[mm][nn * 2 + 1];
                    MMA_BF16(d0, ah[mm][0], ah[mm][1], ah[mm][2], ah[mm][3], bh[nn][0], bh[nn][1]);
                    MMA_BF16(d0, al[mm][0], al[mm][1], al[mm][2], al[mm][3], bh[nn][0], bh[nn][1]);
                    MMA_BF16(d0, ah[mm][0], ah[mm][1], ah[mm][2], ah[mm][3], bl[nn][0], bl[nn][1]);
                    MMA_BF16(d1, ah[mm][0], ah[mm][1], ah[mm][2], ah[mm][3], bh[nn][2], bh[nn][3]);
                    MMA_BF16(d1, al[mm][0], al[mm][1], al[mm][2], al[mm][3], bh[nn][2], bh[nn][3]);
                    MMA_BF16(d1, ah[mm][0], ah[mm][1], ah[mm][2], ah[mm][3], bl[nn][2], bl[nn][3]);
                }
        }
    };

    load_half(0); CP_COMMIT();
    load_half(1); CP_COMMIT();
    asm volatile("cp.async.wait_group 1;" ::: "memory");
    __syncthreads();
    comp_half(0);
    asm volatile("cp.async.wait_group 0;" ::: "memory");
    __syncthreads();
    comp_half(1);

#pragma unroll
    for (int mm = 0; mm < 2; mm++) {
        const int row0 = i0 + wm * 32 + mm * 16 + (lane >> 2);
#pragma unroll
        for (int f = 0; f < 4; f++) {
            const int col = o0 + wn * 32 + f * 8 + (lane & 3) * 2;
            const float b0 = bias[col], b1 = bias[col + 1];
            float y00 = fmaxf(acc[mm][f][0] + b0, 0.f);
            float y01 = fmaxf(acc[mm][f][1] + b1, 0.f);
            float y10 = fmaxf(acc[mm][f][2] + b0, 0.f);
            float y11 = fmaxf(acc[mm][f][3] + b1, 0.f);
            if (outF) {
                *reinterpret_cast<float2*>(outF + (size_t)row0 * DD + col) = make_float2(y00, y01);
                *reinterpret_cast<float2*>(outF + (size_t)(row0 + 8) * DD + col) = make_float2(y10, y11);
            } else {
                float y[4] = {y00, y01, y10, y11};
                __nv_bfloat16 hi[4], lo[4];
#pragma unroll
                for (int j = 0; j < 4; j++) {
                    hi[j] = __float2bfloat16_rn(y[j]);
                    lo[j] = __float2bfloat16_rn(y[j] - __bfloat162float(hi[j]));
                }
                *reinterpret_cast<__nv_bfloat162*>(outHi + (size_t)row0 * DD + col) = __halves2bfloat162(hi[0], hi[1]);
                *reinterpret_cast<__nv_bfloat162*>(outHi + (size_t)(row0 + 8) * DD + col) = __halves2bfloat162(hi[2], hi[3]);
                *reinterpret_cast<__nv_bfloat162*>(outLo + (size_t)row0 * DD + col) = __halves2bfloat162(lo[0], lo[1]);
                *reinterpret_cast<__nv_bfloat162*>(outLo + (size_t)(row0 + 8) * DD + col) = __halves2bfloat162(lo[2], lo[3]);
            }
        }
    }
}

// ==================== launch ====================
extern "C" void kernel_launch(void* const* d_in, const int* in_sizes, int n_in,
                              void* d_out, int out_size) {
    const int*   labels = (const int*)d_in[0];
    const int*   nidx   = (const int*)d_in[1];
    const float* A      = (const float*)d_in[2];
    const float* E      = (const float*)d_in[3];
    const float* W      = (const float*)d_in[4];
    const float* bias   = (const float*)d_in[5];

    float* out        = (float*)d_out;
    float* out_labels = nullptr;
    float* out_h      = out;
    if (out_size >= BB * DD + BB) {
        out_labels = out;
        out_h      = out + BB;
    }

    __nv_bfloat16 *hHi, *hLo, *h2Hi, *h2Lo, *WHi, *WLo;
    cudaGetSymbolAddress((void**)&hHi,  g_hHi);
    cudaGetSymbolAddress((void**)&hLo,  g_hLo);
    cudaGetSymbolAddress((void**)&h2Hi, g_h2Hi);
    cudaGetSymbolAddress((void**)&h2Lo, g_h2Lo);
    cudaGetSymbolAddress((void**)&WHi,  g_WHi);
    cudaGetSymbolAddress((void**)&WLo,  g_WLo);

    cudaFuncSetAttribute(gemm1_kernel,
                         cudaFuncAttributeMaxDynamicSharedMemorySize, GEMM_SMEM);
    cudaFuncSetAttribute(mlp_kernel,
                         cudaFuncAttributeMaxDynamicSharedMemorySize, MLP_SMEM);

    prep_kernel<<<PREP_GRID, 256>>>(labels, nidx, A, E, W, out_labels);
    gemm1_kernel<<<dim3(KSPLIT, BB / MT), 256, GEMM_SMEM>>>();
    finalize_kernel<<<BB, 64>>>(E);
    mlp_kernel<<<dim3(BB / 128, DD / 64), 256, MLP_SMEM>>>(
        hHi, hLo, WHi, WLo, bias, h2Hi, h2Lo, nullptr);
    mlp_kernel<<<dim3(BB / 128, DD / 64), 256, MLP_SMEM>>>(
        h2Hi, h2Lo, WHi + DD * DD, WLo + DD * DD, bias + DD, hHi, hLo, nullptr);
    mlp_kernel<<<dim3(BB / 128, DD / 64), 256, MLP_SMEM>>>(
        hHi, hLo, WHi + 2 * DD * DD, WLo + 2 * DD * DD, bias + 2 * DD,
        nullptr, nullptr, out_h);
}